// round 4
// baseline (speedup 1.0000x reference)
#include <cuda_runtime.h>

#define B_    256
#define NA_   196
#define NB_   196
#define DK_   256
#define DIM_  1024
#define SMOOTH_ 4.0f

// 256*196*196 floats = 39.3 MB scratch for energy/attn (module-load allocation,
// allowed; no runtime alloc).
__device__ float g_attn[(size_t)B_ * NA_ * NB_];

// ---------------------------------------------------------------------------
// Kernel 1: energy[b,a,n] = sum_k Q[b,a,k] * K[b,k,n]
// grid (2, B): x = n-half (98 cols), y = batch. block = 224 (196 active).
// Per-thread micro-tile: 14 (a) x 7 (n), k-chunks of 32.
// ---------------------------------------------------------------------------
__global__ __launch_bounds__(224) void energy_kernel(
    const float* __restrict__ q, const float* __restrict__ kb)
{
    __shared__ float Qs[32][197];   // [k][a], pitch 197 -> conflict-free transp. store
    __shared__ float Ks[32][100];   // [k][n]

    const int b   = blockIdx.y;
    const int n0  = blockIdx.x * 98;
    const int tid = threadIdx.x;
    const int ta  = tid / 14;           // 0..13 for active threads
    const int tn  = tid - ta * 14;      // 0..13
    const bool active = tid < 196;

    const float* __restrict__ qb  = q  + (size_t)b * NA_ * DK_;
    const float* __restrict__ kbb = kb + (size_t)b * DK_ * NB_;

    float acc[14][7];
#pragma unroll
    for (int i = 0; i < 14; i++)
#pragma unroll
        for (int j = 0; j < 7; j++) acc[i][j] = 0.f;

    for (int kc = 0; kc < DK_; kc += 32) {
        // Q tile: read 32 contiguous k per a-row (coalesced), store transposed.
        for (int i = tid; i < NA_ * 32; i += 224) {
            int a = i >> 5, kk = i & 31;
            Qs[kk][a] = qb[a * DK_ + kc + kk];
        }
        // K tile: rows contiguous in n (coalesced).
        for (int i = tid; i < 32 * 98; i += 224) {
            int kk = i / 98, nn = i - kk * 98;
            Ks[kk][nn] = kbb[(kc + kk) * NB_ + n0 + nn];
        }
        __syncthreads();
        if (active) {
#pragma unroll 4
            for (int kk = 0; kk < 32; kk++) {
                float qf[14], kf[7];
#pragma unroll
                for (int i = 0; i < 14; i++) qf[i] = Qs[kk][ta * 14 + i];
#pragma unroll
                for (int j = 0; j < 7; j++)  kf[j] = Ks[kk][tn * 7 + j];
#pragma unroll
                for (int i = 0; i < 14; i++)
#pragma unroll
                    for (int j = 0; j < 7; j++)
                        acc[i][j] = fmaf(qf[i], kf[j], acc[i][j]);
            }
        }
        __syncthreads();
    }

    if (active) {
        float* __restrict__ eb = g_attn + (size_t)b * NA_ * NB_;
#pragma unroll
        for (int i = 0; i < 14; i++) {
            const int a = ta * 14 + i;
#pragma unroll
            for (int j = 0; j < 7; j++)
                eb[a * NB_ + n0 + tn * 7 + j] = acc[i][j];
        }
    }
}

// ---------------------------------------------------------------------------
// Kernel 2: in-place row softmax of SMOOTH * energy over n.
// grid (B), block 256 (8 warps); one warp per row, rows strided by 8.
// ---------------------------------------------------------------------------
__global__ __launch_bounds__(256) void softmax_kernel()
{
    const int b    = blockIdx.x;
    const int warp = threadIdx.x >> 5;
    const int lane = threadIdx.x & 31;
    float* __restrict__ eb = g_attn + (size_t)b * NA_ * NB_;

    for (int a = warp; a < NA_; a += 8) {
        float v[7];
        float m = -1e30f;
#pragma unroll
        for (int i = 0; i < 7; i++) {
            const int n = lane + 32 * i;
            v[i] = (n < NB_) ? eb[a * NB_ + n] : -1e30f;
            m = fmaxf(m, v[i]);
        }
#pragma unroll
        for (int off = 16; off > 0; off >>= 1)
            m = fmaxf(m, __shfl_xor_sync(0xffffffffu, m, off));

        float s = 0.f;
#pragma unroll
        for (int i = 0; i < 7; i++) {
            v[i] = __expf(SMOOTH_ * (v[i] - m));   // masked lanes underflow to 0
            s += v[i];
        }
#pragma unroll
        for (int off = 16; off > 0; off >>= 1)
            s += __shfl_xor_sync(0xffffffffu, s, off);

        const float inv = 1.0f / s;
#pragma unroll
        for (int i = 0; i < 7; i++) {
            const int n = lane + 32 * i;
            if (n < NB_) eb[a * NB_ + n] = v[i] * inv;
        }
    }
}

// ---------------------------------------------------------------------------
// Kernel 3: out[b,d,n] = sum_a V_a[b,d,a] * attn[b,a,n] + value_b[b,d,n] + gamma
// grid (8, B): x = 128-row d-tile, y = batch. block = 224 = 16(d) x 14(n), no
// idle threads. V tile [128 x 196] lives in smem transposed (pitch 132 so the
// 8-wide d-fragment is two aligned float4 LDS.128). attn streamed in
// double-buffered 14-row chunks: 196 = 14 chunks x 14 k, zero remainder.
// Per k-step: 2 LDS.128 + 14 LDS vs 112 FFMA -> FMA-pipe bound.
// ---------------------------------------------------------------------------
#define VSP 132
#define OUT_SMEM_BYTES ((NA_ * VSP + 2 * 14 * NB_) * (int)sizeof(float))

__global__ __launch_bounds__(224) void out_kernel(
    const float* __restrict__ va, const float* __restrict__ vbb,
    const float* __restrict__ gamma, float* __restrict__ out)
{
    extern __shared__ float sm[];
    float* Vs = sm;               // [196][VSP]  (a-major, d inner)
    float* As = sm + NA_ * VSP;   // [2][14][196] double buffer

    const int b   = blockIdx.y;
    const int d0  = blockIdx.x * 128;
    const int tid = threadIdx.x;
    const int td  = tid / 14;          // 0..15
    const int tn  = tid - td * 14;     // 0..13

    const float* __restrict__ vab  = va + ((size_t)b * DIM_ + d0) * NA_;
    const float* __restrict__ attb = g_attn + (size_t)b * NA_ * NB_;

    // Stage whole V tile: gmem reads coalesced along a; smem transposed store.
    for (int i = tid; i < 128 * NA_; i += 224) {
        const int d = i / NA_, a = i - d * NA_;
        Vs[a * VSP + d] = vab[d * NA_ + a];
    }
    // Prefetch attn chunk 0 (contiguous copy).
    for (int i = tid; i < 14 * NB_; i += 224) As[i] = attb[i];
    __syncthreads();

    float acc[8][14];
#pragma unroll
    for (int i = 0; i < 8; i++)
#pragma unroll
        for (int j = 0; j < 14; j++) acc[i][j] = 0.f;

    for (int c = 0; c < 14; c++) {
        // Prefetch next chunk into the other buffer while computing this one.
        if (c + 1 < 14) {
            float* dst = As + ((c + 1) & 1) * (14 * NB_);
            const float* srcp = attb + (size_t)(c + 1) * 14 * NB_;
            for (int i = tid; i < 14 * NB_; i += 224) dst[i] = srcp[i];
        }
        const float* __restrict__ Ab = As + (c & 1) * (14 * NB_);
#pragma unroll 2
        for (int kk = 0; kk < 14; kk++) {
            const int kg = c * 14 + kk;
            float bf[14];
#pragma unroll
            for (int j = 0; j < 14; j++) bf[j] = Ab[kk * NB_ + tn * 14 + j];
            const float4 v0 = *(const float4*)&Vs[kg * VSP + td * 8];
            const float4 v1 = *(const float4*)&Vs[kg * VSP + td * 8 + 4];
            const float vf[8] = {v0.x, v0.y, v0.z, v0.w, v1.x, v1.y, v1.z, v1.w};
#pragma unroll
            for (int i = 0; i < 8; i++)
#pragma unroll
                for (int j = 0; j < 14; j++)
                    acc[i][j] = fmaf(vf[i], bf[j], acc[i][j]);
        }
        __syncthreads();
    }

    const float g = gamma[0];
#pragma unroll
    for (int i = 0; i < 8; i++) {
        const int d = d0 + td * 8 + i;
        const size_t base = ((size_t)b * DIM_ + d) * (size_t)NB_ + tn * 14;
#pragma unroll
        for (int j = 0; j < 14; j++)
            out[base + j] = acc[i][j] + vbb[base + j] + g;
    }
}

// ---------------------------------------------------------------------------
extern "C" void kernel_launch(void* const* d_in, const int* in_sizes, int n_in,
                              void* d_out, int out_size)
{
    (void)in_sizes; (void)n_in; (void)out_size;
    const float* q     = (const float*)d_in[0];  // [B, Na, Dk]
    const float* va    = (const float*)d_in[1];  // [B, Dim, Na]
    const float* kb    = (const float*)d_in[2];  // [B, Dk, Nb]
    const float* vb    = (const float*)d_in[3];  // [B, Dim, Nb]
    const float* gamma = (const float*)d_in[4];  // [1]
    float* out = (float*)d_out;                  // [B, Dim, Nb]

    energy_kernel<<<dim3(2, B_), 224>>>(q, kb);
    softmax_kernel<<<B_, 256>>>();

    // 125,440 B dynamic smem (> 48 KB static limit); attribute set is
    // idempotent, not a stream op, and capture-safe.
    cudaFuncSetAttribute(out_kernel,
                         cudaFuncAttributeMaxDynamicSharedMemorySize,
                         OUT_SMEM_BYTES);
    out_kernel<<<dim3(8, B_), 224, OUT_SMEM_BYTES>>>(va, vb, gamma, out);
}

// round 5
// speedup vs baseline: 2.0939x; 2.0939x over previous
#include <cuda_runtime.h>

#define B_    256
#define NA_   196
#define NB_   196
#define DK_   256
#define DIM_  1024
#define SMOOTH_ 4.0f

// 39.3 MB module-scope scratch for energy/attn (no runtime alloc).
__device__ float g_attn[(size_t)B_ * NA_ * NB_];

// ---------------------------------------------------------------------------
// Kernel 1: energy[b,a,n] = sum_k Q[b,a,k] * K[b,k,n]
// Tile 98x98, block 196 threads (14x14 groups), 7x7 per thread, K-chunks of 32.
// 25.5 KB smem, <=96 regs -> 3 CTAs/SM (21 warps, occ ~33%).
// Per k-step: 14 LDS + 49 FFMA (fma-pipe bound).
// ---------------------------------------------------------------------------
__global__ __launch_bounds__(196, 3) void energy_kernel(
    const float* __restrict__ q, const float* __restrict__ kb)
{
    __shared__ float Qs[32][99];    // [k][a] transposed; pitch 99: conflict-free
    __shared__ float Ks[32][100];   // [k][n]

    const int b   = blockIdx.y;
    const int a0  = (blockIdx.x & 1) * 98;
    const int n0  = (blockIdx.x >> 1) * 98;
    const int tid = threadIdx.x;
    const int ta  = tid / 14;           // 0..13
    const int tn  = tid - ta * 14;      // 0..13

    const float* __restrict__ qb  = q  + ((size_t)b * NA_ + a0) * DK_;
    const float* __restrict__ kbb = kb + (size_t)b * DK_ * NB_ + n0;

    float acc[7][7];
#pragma unroll
    for (int i = 0; i < 7; i++)
#pragma unroll
        for (int j = 0; j < 7; j++) acc[i][j] = 0.f;

    for (int kc = 0; kc < DK_; kc += 32) {
        // Q tile 98(a) x 32(k): 32-float contiguous per row (128B, perfectly
        // coalesced); lane = kk -> transposed store banks 3*kk mod 32: conflict-free.
#pragma unroll
        for (int s = 0; s < 16; s++) {              // 98*32 = 3136 = 16*196
            const int idx = tid + s * 196;
            const int a = idx >> 5, kk = idx & 31;
            Qs[kk][a] = qb[a * DK_ + kc + kk];
        }
        // K tile 32(k) x 98(n): rows contiguous in n.
#pragma unroll
        for (int s = 0; s < 16; s++) {
            const int idx = tid + s * 196;
            const int kk = idx / 98, nn = idx - kk * 98;
            Ks[kk][nn] = kbb[(size_t)(kc + kk) * NB_ + nn];
        }
        __syncthreads();
#pragma unroll 4
        for (int kk = 0; kk < 32; kk++) {
            float qf[7], kf[7];
#pragma unroll
            for (int i = 0; i < 7; i++) qf[i] = Qs[kk][ta * 7 + i];
#pragma unroll
            for (int j = 0; j < 7; j++) kf[j] = Ks[kk][tn * 7 + j];
#pragma unroll
            for (int i = 0; i < 7; i++)
#pragma unroll
                for (int j = 0; j < 7; j++)
                    acc[i][j] = fmaf(qf[i], kf[j], acc[i][j]);
        }
        __syncthreads();
    }

    float* __restrict__ eb = g_attn + (size_t)b * NA_ * NB_;
#pragma unroll
    for (int i = 0; i < 7; i++) {
        const int a = a0 + ta * 7 + i;
#pragma unroll
        for (int j = 0; j < 7; j++)
            eb[(size_t)a * NB_ + n0 + tn * 7 + j] = acc[i][j];
    }
}

// ---------------------------------------------------------------------------
// Kernel 2: in-place row softmax of SMOOTH * energy over n (warp per row).
// ---------------------------------------------------------------------------
__global__ __launch_bounds__(256) void softmax_kernel()
{
    const int b    = blockIdx.x;
    const int warp = threadIdx.x >> 5;
    const int lane = threadIdx.x & 31;
    float* __restrict__ eb = g_attn + (size_t)b * NA_ * NB_;

    for (int a = warp; a < NA_; a += 8) {
        float v[7];
        float m = -1e30f;
#pragma unroll
        for (int i = 0; i < 7; i++) {
            const int n = lane + 32 * i;
            v[i] = (n < NB_) ? eb[a * NB_ + n] : -1e30f;
            m = fmaxf(m, v[i]);
        }
#pragma unroll
        for (int off = 16; off > 0; off >>= 1)
            m = fmaxf(m, __shfl_xor_sync(0xffffffffu, m, off));

        float s = 0.f;
#pragma unroll
        for (int i = 0; i < 7; i++) {
            v[i] = __expf(SMOOTH_ * (v[i] - m));
            s += v[i];
        }
#pragma unroll
        for (int off = 16; off > 0; off >>= 1)
            s += __shfl_xor_sync(0xffffffffu, s, off);

        const float inv = 1.0f / s;
#pragma unroll
        for (int i = 0; i < 7; i++) {
            const int n = lane + 32 * i;
            if (n < NB_) eb[a * NB_ + n] = v[i] * inv;
        }
    }
}

// ---------------------------------------------------------------------------
// Kernel 3: out[b,d,n] = sum_a V_a[b,d,a]*attn[b,a,n] + value_b[b,d,n] + gamma
// Tile 64(d) x 196(n, full width), block 224 = 8(d) x 28(n) groups,
// 8x7 per thread, a-chunks of 49 (4 chunks, exact). 52.5 KB dyn smem,
// <=96 regs -> 3 CTAs/SM. Per k-step: 2 LDS.128 + 7 LDS + 56 FFMA.
// ---------------------------------------------------------------------------
#define VSP 72
#define OUT_SMEM_FLOATS (49 * VSP + 49 * NB_)
#define OUT_SMEM_BYTES  (OUT_SMEM_FLOATS * (int)sizeof(float))

__global__ __launch_bounds__(224, 3) void out_kernel(
    const float* __restrict__ va, const float* __restrict__ vbb,
    const float* __restrict__ gamma, float* __restrict__ out)
{
    extern __shared__ float sm[];
    float* Vs = sm;              // [49][VSP]  transposed ([a][d]), float4-aligned reads
    float* As = sm + 49 * VSP;   // [49][196]  contiguous

    const int b   = blockIdx.y;
    const int d0  = blockIdx.x * 64;
    const int tid = threadIdx.x;
    const int td  = tid / 28;          // 0..7
    const int tn  = tid - td * 28;     // 0..27

    const float* __restrict__ vab  = va + ((size_t)b * DIM_ + d0) * NA_;
    const float* __restrict__ attb = g_attn + (size_t)b * NA_ * NB_;

    float acc[8][7];
#pragma unroll
    for (int i = 0; i < 8; i++)
#pragma unroll
        for (int j = 0; j < 7; j++) acc[i][j] = 0.f;

    for (int c = 0; c < 4; c++) {
        const int ac = c * 49;
        // V chunk 64(d) x 49(a): 49-float contiguous rows; transposed store.
        for (int i = tid; i < 64 * 49; i += 224) {
            const int d = i / 49, a = i - d * 49;
            Vs[a * VSP + d] = vab[(size_t)d * NA_ + ac + a];
        }
        // attn chunk 49 x 196 = 9604 floats = 2401 float4, contiguous copy.
        {
            const float4* __restrict__ src =
                (const float4*)(attb + (size_t)ac * NB_);
            float4* __restrict__ dst = (float4*)As;
            for (int i = tid; i < 2401; i += 224) dst[i] = src[i];
        }
        __syncthreads();
#pragma unroll 2
        for (int kk = 0; kk < 49; kk++) {
            const float4 v0 = *(const float4*)&Vs[kk * VSP + td * 8];
            const float4 v1 = *(const float4*)&Vs[kk * VSP + td * 8 + 4];
            const float vf[8] = {v0.x, v0.y, v0.z, v0.w, v1.x, v1.y, v1.z, v1.w};
            float bf[7];
#pragma unroll
            for (int j = 0; j < 7; j++) bf[j] = As[kk * NB_ + tn * 7 + j];
#pragma unroll
            for (int i = 0; i < 8; i++)
#pragma unroll
                for (int j = 0; j < 7; j++)
                    acc[i][j] = fmaf(vf[i], bf[j], acc[i][j]);
        }
        __syncthreads();
    }

    const float g = gamma[0];
#pragma unroll
    for (int i = 0; i < 8; i++) {
        const size_t base =
            ((size_t)b * DIM_ + d0 + td * 8 + i) * (size_t)NB_ + tn * 7;
#pragma unroll
        for (int j = 0; j < 7; j++)
            out[base + j] = acc[i][j] + vbb[base + j] + g;
    }
}

// ---------------------------------------------------------------------------
extern "C" void kernel_launch(void* const* d_in, const int* in_sizes, int n_in,
                              void* d_out, int out_size)
{
    (void)in_sizes; (void)n_in; (void)out_size;
    const float* q     = (const float*)d_in[0];  // [B, Na, Dk]
    const float* va    = (const float*)d_in[1];  // [B, Dim, Na]
    const float* kb    = (const float*)d_in[2];  // [B, Dk, Nb]
    const float* vb    = (const float*)d_in[3];  // [B, Dim, Nb]
    const float* gamma = (const float*)d_in[4];  // [1]
    float* out = (float*)d_out;                  // [B, Dim, Nb]

    energy_kernel<<<dim3(4, B_), 196>>>(q, kb);
    softmax_kernel<<<B_, 256>>>();

    cudaFuncSetAttribute(out_kernel,
                         cudaFuncAttributeMaxDynamicSharedMemorySize,
                         OUT_SMEM_BYTES);
    out_kernel<<<dim3(16, B_), 224, OUT_SMEM_BYTES>>>(va, vb, gamma, out);
}

// round 6
// speedup vs baseline: 2.3137x; 1.1050x over previous
#include <cuda_runtime.h>

#define B_    256
#define NA_   196
#define NB_   196
#define DK_   256
#define DIM_  1024
#define SMOOTH_ 4.0f

typedef unsigned long long ull;

// Packed dual-fp32 FMA (sm_100+): d.lo += a.lo*b.lo, d.hi += a.hi*b.hi
#define FMA2(d, a, b) \
    asm("fma.rn.f32x2 %0, %1, %2, %0;" : "+l"(d) : "l"(a), "l"(b))
// Splat one float into both halves of a 64-bit packed pair.
#define PACK2(d, x) \
    asm("mov.b64 %0, {%1, %1};" : "=l"(d) : "r"(__float_as_uint(x)))

// 39.3 MB module-scope scratch for energy/attn.
__device__ float g_attn[(size_t)B_ * NA_ * NB_];

// ---------------------------------------------------------------------------
// Kernel 1: energy[b,a,n] = sum_k Q[b,a,k] * K[b,k,n]
// Tile 98(a) x 196(n, full width). Block 196 = 14(ta) x 14(tn).
// Micro-tile 7(a) x 14(n) = 7 packed-n pairs -> 49 FFMA2 per k.
// K-chunks of 32. Qs[a][k] pitch 36 (float4 fills), Ks[k][n] pitch 200.
// kf2 pair loads: 8B-bank = 7*tn+j mod 16, all distinct -> conflict-free.
// ---------------------------------------------------------------------------
__global__ __launch_bounds__(196, 2) void energy_kernel(
    const float* __restrict__ q, const float* __restrict__ kb)
{
    __shared__ float Qs[98 * 36];
    __shared__ float Ks[32 * 200];

    const int b   = blockIdx.y;
    const int a0  = blockIdx.x * 98;
    const int tid = threadIdx.x;
    const int ta  = tid / 14;          // 0..13
    const int tn  = tid - ta * 14;     // 0..13

    const float* __restrict__ qb  = q  + ((size_t)b * NA_ + a0) * DK_;
    const float* __restrict__ kbb = kb + (size_t)b * DK_ * NB_;

    ull acc2[7][7];
#pragma unroll
    for (int i = 0; i < 7; i++)
#pragma unroll
        for (int j = 0; j < 7; j++) acc2[i][j] = 0ULL;

    for (int kc = 0; kc < DK_; kc += 32) {
        // Qs: 98 rows x 8 float4 (row = 32 contiguous k) = 784 = 4*196.
#pragma unroll
        for (int s = 0; s < 4; s++) {
            const int idx = tid + s * 196;
            const int a = idx >> 3, m = idx & 7;
            *(float4*)&Qs[a * 36 + 4 * m] =
                *(const float4*)&qb[a * DK_ + kc + 4 * m];
        }
        // Ks: 32 rows x 49 float4 (196 n) = 1568 = 8*196.
#pragma unroll
        for (int s = 0; s < 8; s++) {
            const int idx = tid + s * 196;
            const int kk = idx / 49, m = idx - kk * 49;
            *(float4*)&Ks[kk * 200 + 4 * m] =
                *(const float4*)&kbb[(size_t)(kc + kk) * NB_ + 4 * m];
        }
        __syncthreads();

#pragma unroll 4
        for (int kp = 0; kp < 16; kp++) {
            float2 qf[7];
#pragma unroll
            for (int i = 0; i < 7; i++)
                qf[i] = *(const float2*)&Qs[(ta * 7 + i) * 36 + 2 * kp];

            ull kf[7], qv[7];
#pragma unroll
            for (int j = 0; j < 7; j++)
                kf[j] = *(const ull*)&Ks[(2 * kp) * 200 + tn * 14 + 2 * j];
#pragma unroll
            for (int i = 0; i < 7; i++) PACK2(qv[i], qf[i].x);
#pragma unroll
            for (int i = 0; i < 7; i++)
#pragma unroll
                for (int j = 0; j < 7; j++) FMA2(acc2[i][j], qv[i], kf[j]);

#pragma unroll
            for (int j = 0; j < 7; j++)
                kf[j] = *(const ull*)&Ks[(2 * kp + 1) * 200 + tn * 14 + 2 * j];
#pragma unroll
            for (int i = 0; i < 7; i++) PACK2(qv[i], qf[i].y);
#pragma unroll
            for (int i = 0; i < 7; i++)
#pragma unroll
                for (int j = 0; j < 7; j++) FMA2(acc2[i][j], qv[i], kf[j]);
        }
        __syncthreads();
    }

    float* __restrict__ eb = g_attn + (size_t)b * NA_ * NB_;
#pragma unroll
    for (int i = 0; i < 7; i++) {
        const size_t base = (size_t)(a0 + ta * 7 + i) * NB_ + tn * 14;
#pragma unroll
        for (int j = 0; j < 7; j++) {
            float2 r;
            r.x = __uint_as_float((unsigned)acc2[i][j]);
            r.y = __uint_as_float((unsigned)(acc2[i][j] >> 32));
            *(float2*)&eb[base + 2 * j] = r;
        }
    }
}

// ---------------------------------------------------------------------------
// Kernel 2: in-place row softmax of SMOOTH * energy over n (warp per row).
// ---------------------------------------------------------------------------
__global__ __launch_bounds__(256) void softmax_kernel()
{
    const int b    = blockIdx.x;
    const int warp = threadIdx.x >> 5;
    const int lane = threadIdx.x & 31;
    float* __restrict__ eb = g_attn + (size_t)b * NA_ * NB_;

    for (int a = warp; a < NA_; a += 8) {
        float v[7];
        float m = -1e30f;
#pragma unroll
        for (int i = 0; i < 7; i++) {
            const int n = lane + 32 * i;
            v[i] = (n < NB_) ? eb[a * NB_ + n] : -1e30f;
            m = fmaxf(m, v[i]);
        }
#pragma unroll
        for (int off = 16; off > 0; off >>= 1)
            m = fmaxf(m, __shfl_xor_sync(0xffffffffu, m, off));

        float s = 0.f;
#pragma unroll
        for (int i = 0; i < 7; i++) {
            v[i] = __expf(SMOOTH_ * (v[i] - m));
            s += v[i];
        }
#pragma unroll
        for (int off = 16; off > 0; off >>= 1)
            s += __shfl_xor_sync(0xffffffffu, s, off);

        const float inv = 1.0f / s;
#pragma unroll
        for (int i = 0; i < 7; i++) {
            const int n = lane + 32 * i;
            if (n < NB_) eb[a * NB_ + n] = v[i] * inv;
        }
    }
}

// ---------------------------------------------------------------------------
// Kernel 3: out[b,d,n] = sum_a V_a[b,d,a]*attn[b,a,n] + value_b[b,d,n] + gamma
// Tile 64(d) x 196(n). Block 224 = 16(td) x 14(tn). Micro 4(d) x 14(n)
// -> 28 FFMA2 per k. a-chunks of 28 (7 exact). Vs[d][a] pitch 28,
// As[a][n] pitch 200 (both float4-fillable, attn read natural layout).
// ~96 regs, 29.6 KB static smem -> 3 CTAs/SM.
// ---------------------------------------------------------------------------
__global__ __launch_bounds__(224, 3) void out_kernel(
    const float* __restrict__ va, const float* __restrict__ vbb,
    const float* __restrict__ gamma, float* __restrict__ out)
{
    __shared__ float Vs[64 * 28];
    __shared__ float As[28 * 200];

    const int b   = blockIdx.y;
    const int d0  = blockIdx.x * 64;
    const int tid = threadIdx.x;
    const int td  = tid / 14;          // 0..15
    const int tn  = tid - td * 14;     // 0..13

    const float* __restrict__ vab  = va + ((size_t)b * DIM_ + d0) * NA_;
    const float* __restrict__ attb = g_attn + (size_t)b * NA_ * NB_;

    ull acc2[4][7];
#pragma unroll
    for (int i = 0; i < 4; i++)
#pragma unroll
        for (int j = 0; j < 7; j++) acc2[i][j] = 0ULL;

    for (int c = 0; c < 7; c++) {
        const int ac = c * 28;
        // Vs: 64 rows x 7 float4 = 448 = 2*224.
#pragma unroll
        for (int s = 0; s < 2; s++) {
            const int idx = tid + s * 224;
            const int d = idx / 7, m = idx - d * 7;
            *(float4*)&Vs[d * 28 + 4 * m] =
                *(const float4*)&vab[(size_t)d * NA_ + ac + 4 * m];
        }
        // As: 28 rows x 49 float4 = 1372.
        for (int i = tid; i < 1372; i += 224) {
            const int kk = i / 49, m = i - kk * 49;
            *(float4*)&As[kk * 200 + 4 * m] =
                *(const float4*)&attb[(size_t)(ac + kk) * NB_ + 4 * m];
        }
        __syncthreads();

#pragma unroll 2
        for (int kp = 0; kp < 14; kp++) {
            float2 vf[4];
#pragma unroll
            for (int i = 0; i < 4; i++)
                vf[i] = *(const float2*)&Vs[(td * 4 + i) * 28 + 2 * kp];

            ull af[7], vv[4];
#pragma unroll
            for (int j = 0; j < 7; j++)
                af[j] = *(const ull*)&As[(2 * kp) * 200 + tn * 14 + 2 * j];
#pragma unroll
            for (int i = 0; i < 4; i++) PACK2(vv[i], vf[i].x);
#pragma unroll
            for (int i = 0; i < 4; i++)
#pragma unroll
                for (int j = 0; j < 7; j++) FMA2(acc2[i][j], vv[i], af[j]);

#pragma unroll
            for (int j = 0; j < 7; j++)
                af[j] = *(const ull*)&As[(2 * kp + 1) * 200 + tn * 14 + 2 * j];
#pragma unroll
            for (int i = 0; i < 4; i++) PACK2(vv[i], vf[i].y);
#pragma unroll
            for (int i = 0; i < 4; i++)
#pragma unroll
                for (int j = 0; j < 7; j++) FMA2(acc2[i][j], vv[i], af[j]);
        }
        __syncthreads();
    }

    const float g = gamma[0];
#pragma unroll
    for (int i = 0; i < 4; i++) {
        const size_t base =
            ((size_t)b * DIM_ + d0 + td * 4 + i) * (size_t)NB_ + tn * 14;
#pragma unroll
        for (int j = 0; j < 7; j++) {
            const float2 w = *(const float2*)&vbb[base + 2 * j];
            float2 r;
            r.x = __uint_as_float((unsigned)acc2[i][j]) + w.x + g;
            r.y = __uint_as_float((unsigned)(acc2[i][j] >> 32)) + w.y + g;
            *(float2*)&out[base + 2 * j] = r;
        }
    }
}

// ---------------------------------------------------------------------------
extern "C" void kernel_launch(void* const* d_in, const int* in_sizes, int n_in,
                              void* d_out, int out_size)
{
    (void)in_sizes; (void)n_in; (void)out_size;
    const float* q     = (const float*)d_in[0];  // [B, Na, Dk]
    const float* va    = (const float*)d_in[1];  // [B, Dim, Na]
    const float* kb    = (const float*)d_in[2];  // [B, Dk, Nb]
    const float* vb    = (const float*)d_in[3];  // [B, Dim, Nb]
    const float* gamma = (const float*)d_in[4];  // [1]
    float* out = (float*)d_out;                  // [B, Dim, Nb]

    energy_kernel<<<dim3(2, B_), 196>>>(q, kb);
    softmax_kernel<<<B_, 256>>>();
    out_kernel<<<dim3(16, B_), 224>>>(va, vb, gamma, out);
}

// round 10
// speedup vs baseline: 4.1143x; 1.7782x over previous
#include <cuda_runtime.h>
#include <cstdint>

#define B_    256
#define NA_   196
#define NB_   196
#define DK_   256
#define DIM_  1024
#define SMOOTH_ 4.0f

typedef unsigned long long ull;

// ---------------- scratch ----------------
__device__ float g_attn[(size_t)B_ * NA_ * NB_];

// ---------------- PTX helpers (all plain sm_80+ PTX, no 'a' features) -------
#define FMA2(d, a, b) \
    asm("fma.rn.f32x2 %0, %1, %2, %0;" : "+l"(d) : "l"(a), "l"(b))
#define PACK2(d, x) \
    asm("mov.b64 %0, {%1, %1};" : "=l"(d) : "r"(__float_as_uint(x)))

__device__ __forceinline__ uint32_t f2tf32(float x) {
    uint32_t u;
    asm("cvt.rna.tf32.f32 %0, %1;" : "=r"(u) : "f"(x));
    return u;
}

// D += A*B for m16n8k8 tf32 (HMMA path, valid on vanilla sm_103 target)
#define MMA16N8K8(c, a, b)                                                    \
    asm volatile(                                                             \
        "mma.sync.aligned.m16n8k8.row.col.f32.tf32.tf32.f32 "                 \
        "{%0,%1,%2,%3}, {%4,%5,%6,%7}, {%8,%9}, {%0,%1,%2,%3};"               \
        : "+f"((c)[0]), "+f"((c)[1]), "+f"((c)[2]), "+f"((c)[3])              \
        : "r"((a)[0]), "r"((a)[1]), "r"((a)[2]), "r"((a)[3]),                 \
          "r"((b)[0]), "r"((b)[1]))

// ---------------------------------------------------------------------------
// Kernel 1: energy (SIMT fp32 with f32x2 packs) — unchanged (proven 250us).
// ---------------------------------------------------------------------------
__global__ __launch_bounds__(196, 2) void energy_kernel(
    const float* __restrict__ q, const float* __restrict__ kb)
{
    __shared__ float Qs[98 * 36];
    __shared__ float Ks[32 * 200];

    const int b   = blockIdx.y;
    const int a0  = blockIdx.x * 98;
    const int tid = threadIdx.x;
    const int ta  = tid / 14;
    const int tn  = tid - ta * 14;

    const float* __restrict__ qb  = q  + ((size_t)b * NA_ + a0) * DK_;
    const float* __restrict__ kbb = kb + (size_t)b * DK_ * NB_;

    ull acc2[7][7];
#pragma unroll
    for (int i = 0; i < 7; i++)
#pragma unroll
        for (int j = 0; j < 7; j++) acc2[i][j] = 0ULL;

    for (int kc = 0; kc < DK_; kc += 32) {
#pragma unroll
        for (int s = 0; s < 4; s++) {
            const int idx = tid + s * 196;
            const int a = idx >> 3, m = idx & 7;
            *(float4*)&Qs[a * 36 + 4 * m] =
                *(const float4*)&qb[a * DK_ + kc + 4 * m];
        }
#pragma unroll
        for (int s = 0; s < 8; s++) {
            const int idx = tid + s * 196;
            const int kk = idx / 49, m = idx - kk * 49;
            *(float4*)&Ks[kk * 200 + 4 * m] =
                *(const float4*)&kbb[(size_t)(kc + kk) * NB_ + 4 * m];
        }
        __syncthreads();

#pragma unroll 4
        for (int kp = 0; kp < 16; kp++) {
            float2 qf[7];
#pragma unroll
            for (int i = 0; i < 7; i++)
                qf[i] = *(const float2*)&Qs[(ta * 7 + i) * 36 + 2 * kp];

            ull kf[7], qv[7];
#pragma unroll
            for (int j = 0; j < 7; j++)
                kf[j] = *(const ull*)&Ks[(2 * kp) * 200 + tn * 14 + 2 * j];
#pragma unroll
            for (int i = 0; i < 7; i++) PACK2(qv[i], qf[i].x);
#pragma unroll
            for (int i = 0; i < 7; i++)
#pragma unroll
                for (int j = 0; j < 7; j++) FMA2(acc2[i][j], qv[i], kf[j]);

#pragma unroll
            for (int j = 0; j < 7; j++)
                kf[j] = *(const ull*)&Ks[(2 * kp + 1) * 200 + tn * 14 + 2 * j];
#pragma unroll
            for (int i = 0; i < 7; i++) PACK2(qv[i], qf[i].y);
#pragma unroll
            for (int i = 0; i < 7; i++)
#pragma unroll
                for (int j = 0; j < 7; j++) FMA2(acc2[i][j], qv[i], kf[j]);
        }
        __syncthreads();
    }

    float* __restrict__ eb = g_attn + (size_t)b * NA_ * NB_;
#pragma unroll
    for (int i = 0; i < 7; i++) {
        const size_t base = (size_t)(a0 + ta * 7 + i) * NB_ + tn * 14;
#pragma unroll
        for (int j = 0; j < 7; j++) {
            float2 r;
            r.x = __uint_as_float((unsigned)acc2[i][j]);
            r.y = __uint_as_float((unsigned)(acc2[i][j] >> 32));
            *(float2*)&eb[base + 2 * j] = r;
        }
    }
}

// ---------------------------------------------------------------------------
// Kernel 2: softmax (unchanged)
// ---------------------------------------------------------------------------
__global__ __launch_bounds__(256) void softmax_kernel()
{
    const int b    = blockIdx.x;
    const int warp = threadIdx.x >> 5;
    const int lane = threadIdx.x & 31;
    float* __restrict__ eb = g_attn + (size_t)b * NA_ * NB_;

    for (int a = warp; a < NA_; a += 8) {
        float v[7];
        float m = -1e30f;
#pragma unroll
        for (int i = 0; i < 7; i++) {
            const int n = lane + 32 * i;
            v[i] = (n < NB_) ? eb[a * NB_ + n] : -1e30f;
            m = fmaxf(m, v[i]);
        }
#pragma unroll
        for (int off = 16; off > 0; off >>= 1)
            m = fmaxf(m, __shfl_xor_sync(0xffffffffu, m, off));

        float s = 0.f;
#pragma unroll
        for (int i = 0; i < 7; i++) {
            v[i] = __expf(SMOOTH_ * (v[i] - m));
            s += v[i];
        }
#pragma unroll
        for (int off = 16; off > 0; off >>= 1)
            s += __shfl_xor_sync(0xffffffffu, s, off);

        const float inv = 1.0f / s;
#pragma unroll
        for (int i = 0; i < 7; i++) {
            const int n = lane + 32 * i;
            if (n < NB_) eb[a * NB_ + n] = v[i] * inv;
        }
    }
}

// ---------------------------------------------------------------------------
// Kernel 3 (mma.sync tf32): out[b,d,n] = V_a@attn + value_b + gamma
// CTA 128 thr = 4 warps (2x2). Tile M=64(d) x N=112(n); n padded to 224,
// k (=a) padded to 224, 7 chunks of 32 zero-filled. Warp tile 32x56 =
// 2x7 m16n8k8 frags. Vs pitch 36 / As pitch 120 -> conflict-free frag LDS.
// attn kept in natural [k][n] layout (B col-major = direct loads, no transp).
// 24.6 KB smem, ~110 regs -> 4 CTAs/SM.
// ---------------------------------------------------------------------------
__global__ __launch_bounds__(128, 4) void out_mma_kernel(
    const float* __restrict__ va, const float* __restrict__ vbb,
    const float* __restrict__ gamma, float* __restrict__ out)
{
    __shared__ uint32_t Vs[64 * 36];    // [d][k] tf32
    __shared__ uint32_t As[32 * 120];   // [k][n] tf32

    const int b   = blockIdx.z;
    const int d0  = blockIdx.x * 64;
    const int n0  = blockIdx.y * 112;
    const int tid = threadIdx.x;
    const int wid = tid >> 5;
    const int lane = tid & 31;
    const int grp = lane >> 2;          // 0..7
    const int tg  = lane & 3;           // 0..3
    const int wm  = wid >> 1;           // 0..1 -> d offset 32*wm
    const int wn  = wid & 1;            // 0..1 -> n offset 56*wn

    const float* __restrict__ vab  = va + ((size_t)b * DIM_ + d0) * NA_;
    const float* __restrict__ attb = g_attn + (size_t)b * NA_ * NB_;

    float acc[2][7][4];
#pragma unroll
    for (int i = 0; i < 2; i++)
#pragma unroll
        for (int j = 0; j < 7; j++)
#pragma unroll
            for (int e = 0; e < 4; e++) acc[i][j][e] = 0.f;

    for (int kc = 0; kc < 224; kc += 32) {
        // ---- Vs: 64 d-rows x 32 k (8 float4 per row) = 512 float4
#pragma unroll
        for (int s = 0; s < 4; s++) {
            const int u = tid + s * 128;
            const int d = u >> 3, m = u & 7;
            float4 v = make_float4(0.f, 0.f, 0.f, 0.f);
            if (kc + 4 * m + 3 < NA_)
                v = *(const float4*)&vab[(size_t)d * NA_ + kc + 4 * m];
            uint32_t* dst = &Vs[d * 36 + 4 * m];
            dst[0] = f2tf32(v.x); dst[1] = f2tf32(v.y);
            dst[2] = f2tf32(v.z); dst[3] = f2tf32(v.w);
        }
        // ---- As: 32 k-rows x 112 n (28 float4 per row) = 896 float4
#pragma unroll
        for (int s = 0; s < 7; s++) {
            const int u = tid + s * 128;
            const int kk = u / 28, m = u - kk * 28;
            const int row = kc + kk;
            float4 v = make_float4(0.f, 0.f, 0.f, 0.f);
            if (row < NA_ && n0 + 4 * m + 3 < NB_)
                v = *(const float4*)&attb[(size_t)row * NB_ + n0 + 4 * m];
            uint32_t* dst = &As[kk * 120 + 4 * m];
            dst[0] = f2tf32(v.x); dst[1] = f2tf32(v.y);
            dst[2] = f2tf32(v.z); dst[3] = f2tf32(v.w);
        }
        __syncthreads();

#pragma unroll
        for (int ks = 0; ks < 4; ks++) {
            const int k0 = ks * 8;
            uint32_t af[2][4];
#pragma unroll
            for (int i = 0; i < 2; i++) {
                const int r = wm * 32 + i * 16 + grp;
                af[i][0] = Vs[r * 36 + k0 + tg];
                af[i][1] = Vs[(r + 8) * 36 + k0 + tg];
                af[i][2] = Vs[r * 36 + k0 + tg + 4];
                af[i][3] = Vs[(r + 8) * 36 + k0 + tg + 4];
            }
            uint32_t bf[7][2];
#pragma unroll
            for (int j = 0; j < 7; j++) {
                const int col = wn * 56 + j * 8 + grp;
                bf[j][0] = As[(k0 + tg) * 120 + col];
                bf[j][1] = As[(k0 + tg + 4) * 120 + col];
            }
#pragma unroll
            for (int i = 0; i < 2; i++)
#pragma unroll
                for (int j = 0; j < 7; j++)
                    MMA16N8K8(acc[i][j], af[i], bf[j]);
        }
        __syncthreads();
    }

    // ---- epilogue: fused + value_b + gamma, direct stores (8B per thread)
    const float g0 = gamma[0];
#pragma unroll
    for (int i = 0; i < 2; i++) {
        const int row = d0 + wm * 32 + i * 16 + grp;
#pragma unroll
        for (int j = 0; j < 7; j++) {
            const int col = n0 + wn * 56 + j * 8 + tg * 2;
            if (col < NB_) {
                const size_t o  = ((size_t)b * DIM_ + row) * NB_ + col;
                const size_t o2 = o + (size_t)8 * NB_;
                const float2 w  = *(const float2*)&vbb[o];
                const float2 w2 = *(const float2*)&vbb[o2];
                float2 r, r2;
                r.x  = acc[i][j][0] + w.x  + g0;
                r.y  = acc[i][j][1] + w.y  + g0;
                r2.x = acc[i][j][2] + w2.x + g0;
                r2.y = acc[i][j][3] + w2.y + g0;
                *(float2*)&out[o]  = r;
                *(float2*)&out[o2] = r2;
            }
        }
    }
}

// ---------------------------------------------------------------------------
extern "C" void kernel_launch(void* const* d_in, const int* in_sizes, int n_in,
                              void* d_out, int out_size)
{
    (void)in_sizes; (void)n_in; (void)out_size;
    const float* q     = (const float*)d_in[0];  // [B, Na, Dk]
    const float* va    = (const float*)d_in[1];  // [B, Dim, Na]
    const float* kb    = (const float*)d_in[2];  // [B, Dk, Nb]
    const float* vb    = (const float*)d_in[3];  // [B, Dim, Nb]
    const float* gamma = (const float*)d_in[4];  // [1]
    float* out = (float*)d_out;                  // [B, Dim, Nb]

    energy_kernel<<<dim3(2, B_), 196>>>(q, kb);
    softmax_kernel<<<B_, 256>>>();
    out_mma_kernel<<<dim3(16, 2, B_), 128>>>(va, vb, gamma, out);
}

// round 12
// speedup vs baseline: 5.4893x; 1.3342x over previous
#include <cuda_runtime.h>
#include <cuda_bf16.h>
#include <cstdint>

#define B_    256
#define NA_   196
#define NB_   196
#define DK_   256
#define DIM_  1024
#define SMOOTH_ 4.0f

typedef unsigned long long ull;

// ---------------- scratch ----------------
__device__ float g_attn[(size_t)B_ * NA_ * NB_];
// chunk-blocked bf16 hi/lo copies: [b][c(=k/32)][row(224)][kk(32)]
__device__ __nv_bfloat16 g_qh[(size_t)B_ * 8 * 224 * 32];
__device__ __nv_bfloat16 g_ql[(size_t)B_ * 8 * 224 * 32];
__device__ __nv_bfloat16 g_kh[(size_t)B_ * 8 * 224 * 32];
__device__ __nv_bfloat16 g_kl[(size_t)B_ * 8 * 224 * 32];

// ---------------- PTX helpers (plain sm_80+ PTX only) ----------------
__device__ __forceinline__ uint32_t f2tf32(float x) {
    uint32_t u;
    asm("cvt.rna.tf32.f32 %0, %1;" : "=r"(u) : "f"(x));
    return u;
}

#define MMA_TF32(c, a, b)                                                     \
    asm volatile(                                                             \
        "mma.sync.aligned.m16n8k8.row.col.f32.tf32.tf32.f32 "                 \
        "{%0,%1,%2,%3}, {%4,%5,%6,%7}, {%8,%9}, {%0,%1,%2,%3};"               \
        : "+f"((c)[0]), "+f"((c)[1]), "+f"((c)[2]), "+f"((c)[3])              \
        : "r"((a)[0]), "r"((a)[1]), "r"((a)[2]), "r"((a)[3]),                 \
          "r"((b)[0]), "r"((b)[1]))

#define MMA_BF16(c, a, b)                                                     \
    asm volatile(                                                             \
        "mma.sync.aligned.m16n8k16.row.col.f32.bf16.bf16.f32 "                \
        "{%0,%1,%2,%3}, {%4,%5,%6,%7}, {%8,%9}, {%0,%1,%2,%3};"               \
        : "+f"((c)[0]), "+f"((c)[1]), "+f"((c)[2]), "+f"((c)[3])              \
        : "r"((a)[0]), "r"((a)[1]), "r"((a)[2]), "r"((a)[3]),                 \
          "r"((b)[0]), "r"((b)[1]))

__device__ __forceinline__ void bf16_split(float v, __nv_bfloat16& h,
                                           __nv_bfloat16& l) {
    h = __float2bfloat16_rn(v);
    l = __float2bfloat16_rn(v - __bfloat162float(h));
}

// ---------------------------------------------------------------------------
// convQ: Q[b][a][k] fp32 -> g_qh/g_ql[b][c][a][kk] bf16 (a padded to 224).
// grid (8, B), 256 thr. Reads coalesced along k, writes contiguous.
// ---------------------------------------------------------------------------
__global__ __launch_bounds__(256) void convq_kernel(const float* __restrict__ q)
{
    const int c = blockIdx.x, b = blockIdx.y;
    const size_t obase = ((size_t)(b * 8 + c)) * 224 * 32;
    const float* __restrict__ qb = q + (size_t)b * NA_ * DK_ + c * 32;

    for (int i = threadIdx.x; i < 224 * 32; i += 256) {
        const int a = i >> 5, kk = i & 31;
        float v = 0.f;
        if (a < NA_) v = qb[(size_t)a * DK_ + kk];
        __nv_bfloat16 h, l;
        bf16_split(v, h, l);
        g_qh[obase + i] = h;
        g_ql[obase + i] = l;
    }
}

// ---------------------------------------------------------------------------
// convK: K[b][k][n] fp32 -> transposed g_kh/g_kl[b][c][n][kk] bf16
// (n padded to 224). smem 32x225 transpose tile; conflict-free both ways.
// ---------------------------------------------------------------------------
__global__ __launch_bounds__(256) void convk_kernel(const float* __restrict__ kb)
{
    __shared__ float T[32 * 225];
    const int c = blockIdx.x, b = blockIdx.y;
    const size_t obase = ((size_t)(b * 8 + c)) * 224 * 32;
    const float* __restrict__ kbb = kb + ((size_t)b * DK_ + c * 32) * NB_;

    for (int i = threadIdx.x; i < 32 * 224; i += 256) {
        const int kk = i / 224, n = i - kk * 224;
        T[kk * 225 + n] = (n < NB_) ? kbb[(size_t)kk * NB_ + n] : 0.f;
    }
    __syncthreads();
    for (int i = threadIdx.x; i < 224 * 32; i += 256) {
        const int n = i >> 5, kk = i & 31;
        __nv_bfloat16 h, l;
        bf16_split(T[kk * 225 + n], h, l);
        g_kh[obase + i] = h;
        g_kl[obase + i] = l;
    }
}

// ---------------------------------------------------------------------------
// energy+softmax (bf16-split HMMA): attn[b,a,:] = softmax(4 * Q K) rows.
// CTA = 32(a) x 224(n full width), 4 warps (each n-slab of 56), k = 8 chunks
// of 32. Per (i,j,s): 3 MMAs (qh*kh + qh*kl + ql*kh). Frag smem pitch 20
// words -> conflict-free LDS. Epilogue: C->smem (aliased) -> warp softmax
// (8 rows/warp) -> g_attn. Smem 40960 B static.
// ---------------------------------------------------------------------------
#define EP 20   // words per row (16 data + 4 pad)

__global__ __launch_bounds__(128, 4) void energy_mma_kernel()
{
    __shared__ uint32_t SM[10240];              // 40960 B
    uint32_t* Kh = SM;                          // 224*20 = 4480
    uint32_t* Kl = SM + 4480;
    uint32_t* Qh = SM + 8960;                   // 32*20 = 640
    uint32_t* Ql = SM + 9600;
    float*    Es = (float*)SM;                  // epilogue alias, 32*228

    const int b    = blockIdx.y;
    const int a0   = blockIdx.x * 32;
    const int tid  = threadIdx.x;
    const int wid  = tid >> 5;
    const int lane = tid & 31;
    const int grp  = lane >> 2;
    const int tg   = lane & 3;
    const int wc   = wid * 56;                  // warp n-offset

    float acc[2][7][4];
#pragma unroll
    for (int i = 0; i < 2; i++)
#pragma unroll
        for (int j = 0; j < 7; j++)
#pragma unroll
            for (int e = 0; e < 4; e++) acc[i][j][e] = 0.f;

    for (int c = 0; c < 8; c++) {
        const size_t kb0 = ((size_t)(b * 8 + c)) * 224 * 32;        // halves
        const size_t qb0 = kb0 + (size_t)a0 * 32;
        const uint4* __restrict__ skh = (const uint4*)(g_kh + kb0);
        const uint4* __restrict__ skl = (const uint4*)(g_kl + kb0);
        const uint4* __restrict__ sqh = (const uint4*)(g_qh + qb0);
        const uint4* __restrict__ sql = (const uint4*)(g_ql + qb0);

        // K chunk: 224 rows x 4 uint4 = 896; Q chunk: 32 x 4 = 128.
#pragma unroll
        for (int s = 0; s < 7; s++) {
            const int u = tid + s * 128;
            const int n = u >> 2, qq = u & 3;
            *(uint4*)&Kh[n * EP + 4 * qq] = skh[u];
            *(uint4*)&Kl[n * EP + 4 * qq] = skl[u];
        }
        {
            const int a = tid >> 2, qq = tid & 3;
            *(uint4*)&Qh[a * EP + 4 * qq] = sqh[tid];
            *(uint4*)&Ql[a * EP + 4 * qq] = sql[tid];
        }
        __syncthreads();

#pragma unroll
        for (int s = 0; s < 2; s++) {
            const int w0 = s * 8 + tg;
            uint32_t ah[2][4], al[2][4];
#pragma unroll
            for (int i = 0; i < 2; i++) {
                const int r = i * 16 + grp;
                ah[i][0] = Qh[r * EP + w0];       al[i][0] = Ql[r * EP + w0];
                ah[i][1] = Qh[(r + 8) * EP + w0]; al[i][1] = Ql[(r + 8) * EP + w0];
                ah[i][2] = Qh[r * EP + w0 + 4];   al[i][2] = Ql[r * EP + w0 + 4];
                ah[i][3] = Qh[(r + 8) * EP + w0 + 4];
                al[i][3] = Ql[(r + 8) * EP + w0 + 4];
            }
            uint32_t bh[7][2], bl[7][2];
#pragma unroll
            for (int j = 0; j < 7; j++) {
                const int col = wc + j * 8 + grp;
                bh[j][0] = Kh[col * EP + w0];     bl[j][0] = Kl[col * EP + w0];
                bh[j][1] = Kh[col * EP + w0 + 4]; bl[j][1] = Kl[col * EP + w0 + 4];
            }
#pragma unroll
            for (int i = 0; i < 2; i++)
#pragma unroll
                for (int j = 0; j < 7; j++) {
                    MMA_BF16(acc[i][j], ah[i], bh[j]);
                    MMA_BF16(acc[i][j], ah[i], bl[j]);
                    MMA_BF16(acc[i][j], al[i], bh[j]);
                }
        }
        __syncthreads();
    }

    // ---- epilogue: C frags -> Es (aliased smem) ----
#pragma unroll
    for (int i = 0; i < 2; i++) {
#pragma unroll
        for (int j = 0; j < 7; j++) {
            const int col = wc + j * 8 + 2 * tg;
            const int r0 = i * 16 + grp;
            *(float2*)&Es[r0 * 228 + col] =
                make_float2(acc[i][j][0], acc[i][j][1]);
            *(float2*)&Es[(r0 + 8) * 228 + col] =
                make_float2(acc[i][j][2], acc[i][j][3]);
        }
    }
    __syncthreads();

    // ---- fused softmax: warp w handles rows 8w..8w+7 ----
    float* __restrict__ attb = g_attn + (size_t)b * NA_ * NB_;
#pragma unroll
    for (int rr = 0; rr < 8; rr++) {
        const int row = wid * 8 + rr;
        const int a = a0 + row;
        if (a >= NA_) break;
        float v[7];
        float m = -1e30f;
#pragma unroll
        for (int t = 0; t < 7; t++) {
            const int n = lane + 32 * t;
            v[t] = (n < NB_) ? Es[row * 228 + n] : -1e30f;
            m = fmaxf(m, v[t]);
        }
#pragma unroll
        for (int off = 16; off > 0; off >>= 1)
            m = fmaxf(m, __shfl_xor_sync(0xffffffffu, m, off));
        float s = 0.f;
#pragma unroll
        for (int t = 0; t < 7; t++) {
            v[t] = __expf(SMOOTH_ * (v[t] - m));
            s += v[t];
        }
#pragma unroll
        for (int off = 16; off > 0; off >>= 1)
            s += __shfl_xor_sync(0xffffffffu, s, off);
        const float inv = 1.0f / s;
#pragma unroll
        for (int t = 0; t < 7; t++) {
            const int n = lane + 32 * t;
            if (n < NB_) attb[(size_t)a * NB_ + n] = v[t] * inv;
        }
    }
}

// ---------------------------------------------------------------------------
// Kernel 3 (mma.sync tf32): out = V_a@attn + value_b + gamma  (unchanged,
// proven ~270us in round 10).
// ---------------------------------------------------------------------------
__global__ __launch_bounds__(128, 4) void out_mma_kernel(
    const float* __restrict__ va, const float* __restrict__ vbb,
    const float* __restrict__ gamma, float* __restrict__ out)
{
    __shared__ uint32_t Vs[64 * 36];    // [d][k] tf32
    __shared__ uint32_t As[32 * 120];   // [k][n] tf32

    const int b   = blockIdx.z;
    const int d0  = blockIdx.x * 64;
    const int n0  = blockIdx.y * 112;
    const int tid = threadIdx.x;
    const int wid = tid >> 5;
    const int lane = tid & 31;
    const int grp = lane >> 2;
    const int tg  = lane & 3;
    const int wm  = wid >> 1;
    const int wn  = wid & 1;

    const float* __restrict__ vab  = va + ((size_t)b * DIM_ + d0) * NA_;
    const float* __restrict__ attb = g_attn + (size_t)b * NA_ * NB_;

    float acc[2][7][4];
#pragma unroll
    for (int i = 0; i < 2; i++)
#pragma unroll
        for (int j = 0; j < 7; j++)
#pragma unroll
            for (int e = 0; e < 4; e++) acc[i][j][e] = 0.f;

    for (int kc = 0; kc < 224; kc += 32) {
#pragma unroll
        for (int s = 0; s < 4; s++) {
            const int u = tid + s * 128;
            const int d = u >> 3, m = u & 7;
            float4 v = make_float4(0.f, 0.f, 0.f, 0.f);
            if (kc + 4 * m + 3 < NA_)
                v = *(const float4*)&vab[(size_t)d * NA_ + kc + 4 * m];
            uint32_t* dst = &Vs[d * 36 + 4 * m];
            dst[0] = f2tf32(v.x); dst[1] = f2tf32(v.y);
            dst[2] = f2tf32(v.z); dst[3] = f2tf32(v.w);
        }
#pragma unroll
        for (int s = 0; s < 7; s++) {
            const int u = tid + s * 128;
            const int kk = u / 28, m = u - kk * 28;
            const int row = kc + kk;
            float4 v = make_float4(0.f, 0.f, 0.f, 0.f);
            if (row < NA_ && n0 + 4 * m + 3 < NB_)
                v = *(const float4*)&attb[(size_t)row * NB_ + n0 + 4 * m];
            uint32_t* dst = &As[kk * 120 + 4 * m];
            dst[0] = f2tf32(v.x); dst[1] = f2tf32(v.y);
            dst[2] = f2tf32(v.z); dst[3] = f2tf32(v.w);
        }
        __syncthreads();

#pragma unroll
        for (int ks = 0; ks < 4; ks++) {
            const int k0 = ks * 8;
            uint32_t af[2][4];
#pragma unroll
            for (int i = 0; i < 2; i++) {
                const int r = wm * 32 + i * 16 + grp;
                af[i][0] = Vs[r * 36 + k0 + tg];
                af[i][1] = Vs[(r + 8) * 36 + k0 + tg];
                af[i][2] = Vs[r * 36 + k0 + tg + 4];
                af[i][3] = Vs[(r + 8) * 36 + k0 + tg + 4];
            }
            uint32_t bf[7][2];
#pragma unroll
            for (int j = 0; j < 7; j++) {
                const int col = wn * 56 + j * 8 + grp;
                bf[j][0] = As[(k0 + tg) * 120 + col];
                bf[j][1] = As[(k0 + tg + 4) * 120 + col];
            }
#pragma unroll
            for (int i = 0; i < 2; i++)
#pragma unroll
                for (int j = 0; j < 7; j++)
                    MMA_TF32(acc[i][j], af[i], bf[j]);
        }
        __syncthreads();
    }

    const float g0 = gamma[0];
#pragma unroll
    for (int i = 0; i < 2; i++) {
        const int row = d0 + wm * 32 + i * 16 + grp;
#pragma unroll
        for (int j = 0; j < 7; j++) {
            const int col = n0 + wn * 56 + j * 8 + tg * 2;
            if (col < NB_) {
                const size_t o  = ((size_t)b * DIM_ + row) * NB_ + col;
                const size_t o2 = o + (size_t)8 * NB_;
                const float2 w  = *(const float2*)&vbb[o];
                const float2 w2 = *(const float2*)&vbb[o2];
                float2 r, r2;
                r.x  = acc[i][j][0] + w.x  + g0;
                r.y  = acc[i][j][1] + w.y  + g0;
                r2.x = acc[i][j][2] + w2.x + g0;
                r2.y = acc[i][j][3] + w2.y + g0;
                *(float2*)&out[o]  = r;
                *(float2*)&out[o2] = r2;
            }
        }
    }
}

// ---------------------------------------------------------------------------
extern "C" void kernel_launch(void* const* d_in, const int* in_sizes, int n_in,
                              void* d_out, int out_size)
{
    (void)in_sizes; (void)n_in; (void)out_size;
    const float* q     = (const float*)d_in[0];  // [B, Na, Dk]
    const float* va    = (const float*)d_in[1];  // [B, Dim, Na]
    const float* kb    = (const float*)d_in[2];  // [B, Dk, Nb]
    const float* vb    = (const float*)d_in[3];  // [B, Dim, Nb]
    const float* gamma = (const float*)d_in[4];  // [1]
    float* out = (float*)d_out;                  // [B, Dim, Nb]

    convq_kernel<<<dim3(8, B_), 256>>>(q);
    convk_kernel<<<dim3(8, B_), 256>>>(kb);
    energy_mma_kernel<<<dim3(7, B_), 128>>>();
    out_mma_kernel<<<dim3(16, 2, B_), 128>>>(va, vb, gamma, out);
}

// round 15
// speedup vs baseline: 6.7210x; 1.2244x over previous
#include <cuda_runtime.h>
#include <cuda_bf16.h>
#include <cstdint>

#define B_    256
#define NA_   196
#define NB_   196
#define DK_   256
#define DIM_  1024
#define SMOOTH_ 4.0f

typedef unsigned long long ull;

// ---------------- scratch ----------------
// attn stored as tf32-rounded fp32 bit patterns (consumed raw by mma.tf32).
__device__ float g_attn[(size_t)B_ * NA_ * NB_];
// chunk-blocked bf16 hi/lo copies: [b][c(=k/32)][row(224)][kk(32)]
__device__ __nv_bfloat16 g_qh[(size_t)B_ * 8 * 224 * 32];
__device__ __nv_bfloat16 g_ql[(size_t)B_ * 8 * 224 * 32];
__device__ __nv_bfloat16 g_kh[(size_t)B_ * 8 * 224 * 32];
__device__ __nv_bfloat16 g_kl[(size_t)B_ * 8 * 224 * 32];

// ---------------- PTX helpers (plain sm_80+ PTX only) ----------------
__device__ __forceinline__ uint32_t f2tf32(float x) {
    uint32_t u;
    asm("cvt.rna.tf32.f32 %0, %1;" : "=r"(u) : "f"(x));
    return u;
}
__device__ __forceinline__ uint32_t smem_u32(const void* p) {
    uint32_t a;
    asm("{ .reg .u64 t; cvta.to.shared.u64 t, %1; cvt.u32.u64 %0, t; }"
        : "=r"(a) : "l"(p));
    return a;
}

#define CP_ASYNC16(dst, src, sz)                                              \
    asm volatile("cp.async.cg.shared.global [%0], [%1], 16, %2;"              \
        :: "r"(dst), "l"(src), "r"(sz) : "memory")
#define CP_COMMIT()  asm volatile("cp.async.commit_group;" ::: "memory")
#define CP_WAIT1()   asm volatile("cp.async.wait_group 1;" ::: "memory")
#define CP_WAIT0()   asm volatile("cp.async.wait_group 0;" ::: "memory")

#define MMA_TF32(c, a, b)                                                     \
    asm volatile(                                                             \
        "mma.sync.aligned.m16n8k8.row.col.f32.tf32.tf32.f32 "                 \
        "{%0,%1,%2,%3}, {%4,%5,%6,%7}, {%8,%9}, {%0,%1,%2,%3};"               \
        : "+f"((c)[0]), "+f"((c)[1]), "+f"((c)[2]), "+f"((c)[3])              \
        : "r"((a)[0]), "r"((a)[1]), "r"((a)[2]), "r"((a)[3]),                 \
          "r"((b)[0]), "r"((b)[1]))

#define MMA_BF16(c, a, b)                                                     \
    asm volatile(                                                             \
        "mma.sync.aligned.m16n8k16.row.col.f32.bf16.bf16.f32 "                \
        "{%0,%1,%2,%3}, {%4,%5,%6,%7}, {%8,%9}, {%0,%1,%2,%3};"               \
        : "+f"((c)[0]), "+f"((c)[1]), "+f"((c)[2]), "+f"((c)[3])              \
        : "r"((a)[0]), "r"((a)[1]), "r"((a)[2]), "r"((a)[3]),                 \
          "r"((b)[0]), "r"((b)[1]))

__device__ __forceinline__ void bf16_split(float v, __nv_bfloat16& h,
                                           __nv_bfloat16& l) {
    h = __float2bfloat16_rn(v);
    l = __float2bfloat16_rn(v - __bfloat162float(h));
}

// ---------------------------------------------------------------------------
// convQ: Q[b][a][k] fp32 -> g_qh/g_ql[b][c][a][kk] bf16 (a padded to 224).
// ---------------------------------------------------------------------------
__global__ __launch_bounds__(256) void convq_kernel(const float* __restrict__ q)
{
    const int c = blockIdx.x, b = blockIdx.y;
    const size_t obase = ((size_t)(b * 8 + c)) * 224 * 32;
    const float* __restrict__ qb = q + (size_t)b * NA_ * DK_ + c * 32;

    for (int i = threadIdx.x; i < 224 * 32; i += 256) {
        const int a = i >> 5, kk = i & 31;
        float v = 0.f;
        if (a < NA_) v = qb[(size_t)a * DK_ + kk];
        __nv_bfloat16 h, l;
        bf16_split(v, h, l);
        g_qh[obase + i] = h;
        g_ql[obase + i] = l;
    }
}

// ---------------------------------------------------------------------------
// convK: K[b][k][n] fp32 -> transposed g_kh/g_kl[b][c][n][kk] bf16.
// ---------------------------------------------------------------------------
__global__ __launch_bounds__(256) void convk_kernel(const float* __restrict__ kb)
{
    __shared__ float T[32 * 225];
    const int c = blockIdx.x, b = blockIdx.y;
    const size_t obase = ((size_t)(b * 8 + c)) * 224 * 32;
    const float* __restrict__ kbb = kb + ((size_t)b * DK_ + c * 32) * NB_;

    for (int i = threadIdx.x; i < 32 * 224; i += 256) {
        const int kk = i / 224, n = i - kk * 224;
        T[kk * 225 + n] = (n < NB_) ? kbb[(size_t)kk * NB_ + n] : 0.f;
    }
    __syncthreads();
    for (int i = threadIdx.x; i < 224 * 32; i += 256) {
        const int n = i >> 5, kk = i & 31;
        __nv_bfloat16 h, l;
        bf16_split(T[kk * 225 + n], h, l);
        g_kh[obase + i] = h;
        g_kl[obase + i] = l;
    }
}

// ---------------------------------------------------------------------------
// energy+softmax (bf16-split HMMA) — unchanged except the attn store is
// rna-rounded to tf32 bits (free; dedups 16x cvt work in out_mma).
// ---------------------------------------------------------------------------
#define EP 20

__global__ __launch_bounds__(128, 4) void energy_mma_kernel()
{
    __shared__ uint32_t SM[10240];
    uint32_t* Kh = SM;
    uint32_t* Kl = SM + 4480;
    uint32_t* Qh = SM + 8960;
    uint32_t* Ql = SM + 9600;
    float*    Es = (float*)SM;

    const int b    = blockIdx.y;
    const int a0   = blockIdx.x * 32;
    const int tid  = threadIdx.x;
    const int wid  = tid >> 5;
    const int lane = tid & 31;
    const int grp  = lane >> 2;
    const int tg   = lane & 3;
    const int wc   = wid * 56;

    float acc[2][7][4];
#pragma unroll
    for (int i = 0; i < 2; i++)
#pragma unroll
        for (int j = 0; j < 7; j++)
#pragma unroll
            for (int e = 0; e < 4; e++) acc[i][j][e] = 0.f;

    for (int c = 0; c < 8; c++) {
        const size_t kb0 = ((size_t)(b * 8 + c)) * 224 * 32;
        const size_t qb0 = kb0 + (size_t)a0 * 32;
        const uint4* __restrict__ skh = (const uint4*)(g_kh + kb0);
        const uint4* __restrict__ skl = (const uint4*)(g_kl + kb0);
        const uint4* __restrict__ sqh = (const uint4*)(g_qh + qb0);
        const uint4* __restrict__ sql = (const uint4*)(g_ql + qb0);

#pragma unroll
        for (int s = 0; s < 7; s++) {
            const int u = tid + s * 128;
            const int n = u >> 2, qq = u & 3;
            *(uint4*)&Kh[n * EP + 4 * qq] = skh[u];
            *(uint4*)&Kl[n * EP + 4 * qq] = skl[u];
        }
        {
            const int a = tid >> 2, qq = tid & 3;
            *(uint4*)&Qh[a * EP + 4 * qq] = sqh[tid];
            *(uint4*)&Ql[a * EP + 4 * qq] = sql[tid];
        }
        __syncthreads();

#pragma unroll
        for (int s = 0; s < 2; s++) {
            const int w0 = s * 8 + tg;
            uint32_t ah[2][4], al[2][4];
#pragma unroll
            for (int i = 0; i < 2; i++) {
                const int r = i * 16 + grp;
                ah[i][0] = Qh[r * EP + w0];       al[i][0] = Ql[r * EP + w0];
                ah[i][1] = Qh[(r + 8) * EP + w0]; al[i][1] = Ql[(r + 8) * EP + w0];
                ah[i][2] = Qh[r * EP + w0 + 4];   al[i][2] = Ql[r * EP + w0 + 4];
                ah[i][3] = Qh[(r + 8) * EP + w0 + 4];
                al[i][3] = Ql[(r + 8) * EP + w0 + 4];
            }
            uint32_t bh[7][2], bl[7][2];
#pragma unroll
            for (int j = 0; j < 7; j++) {
                const int col = wc + j * 8 + grp;
                bh[j][0] = Kh[col * EP + w0];     bl[j][0] = Kl[col * EP + w0];
                bh[j][1] = Kh[col * EP + w0 + 4]; bl[j][1] = Kl[col * EP + w0 + 4];
            }
#pragma unroll
            for (int i = 0; i < 2; i++)
#pragma unroll
                for (int j = 0; j < 7; j++) {
                    MMA_BF16(acc[i][j], ah[i], bh[j]);
                    MMA_BF16(acc[i][j], ah[i], bl[j]);
                    MMA_BF16(acc[i][j], al[i], bh[j]);
                }
        }
        __syncthreads();
    }

#pragma unroll
    for (int i = 0; i < 2; i++) {
#pragma unroll
        for (int j = 0; j < 7; j++) {
            const int col = wc + j * 8 + 2 * tg;
            const int r0 = i * 16 + grp;
            *(float2*)&Es[r0 * 228 + col] =
                make_float2(acc[i][j][0], acc[i][j][1]);
            *(float2*)&Es[(r0 + 8) * 228 + col] =
                make_float2(acc[i][j][2], acc[i][j][3]);
        }
    }
    __syncthreads();

    float* __restrict__ attb = g_attn + (size_t)b * NA_ * NB_;
#pragma unroll
    for (int rr = 0; rr < 8; rr++) {
        const int row = wid * 8 + rr;
        const int a = a0 + row;
        if (a >= NA_) break;
        float v[7];
        float m = -1e30f;
#pragma unroll
        for (int t = 0; t < 7; t++) {
            const int n = lane + 32 * t;
            v[t] = (n < NB_) ? Es[row * 228 + n] : -1e30f;
            m = fmaxf(m, v[t]);
        }
#pragma unroll
        for (int off = 16; off > 0; off >>= 1)
            m = fmaxf(m, __shfl_xor_sync(0xffffffffu, m, off));
        float s = 0.f;
#pragma unroll
        for (int t = 0; t < 7; t++) {
            v[t] = __expf(SMOOTH_ * (v[t] - m));
            s += v[t];
        }
#pragma unroll
        for (int off = 16; off > 0; off >>= 1)
            s += __shfl_xor_sync(0xffffffffu, s, off);
        const float inv = 1.0f / s;
#pragma unroll
        for (int t = 0; t < 7; t++) {
            const int n = lane + 32 * t;
            if (n < NB_)
                attb[(size_t)a * NB_ + n] =
                    __uint_as_float(f2tf32(v[t] * inv));
        }
    }
}

// ---------------------------------------------------------------------------
// Kernel 3 (mma.sync tf32, cp.async double-buffered): out = V@attn + vb + g.
// No cvt anywhere: attn is pre-tf32 (exact), V fed as raw fp32 bits (HW
// truncates to tf32). Both tiles filled with cp.async.cg 16B (+zfill pads),
// chunk c+1 loads overlap chunk c's 56 MMAs. 48 KB dyn smem, 4 CTAs/SM.
// Buffer layout (words): buf p at p*6144: Vs[64*36] then As[32*120].
// ---------------------------------------------------------------------------
#define OB_WORDS 6144
#define OUT_SMEM_BYTES (2 * OB_WORDS * 4)

__global__ __launch_bounds__(128, 4) void out_mma_kernel(
    const float* __restrict__ va, const float* __restrict__ vbb,
    const float* __restrict__ gamma, float* __restrict__ out)
{
    extern __shared__ uint32_t DYN[];
    const uint32_t sbase = smem_u32(DYN);

    const int b   = blockIdx.z;
    const int d0  = blockIdx.x * 64;
    const int n0  = blockIdx.y * 112;
    const int tid = threadIdx.x;
    const int wid = tid >> 5;
    const int lane = tid & 31;
    const int grp = lane >> 2;
    const int tg  = lane & 3;
    const int wm  = wid >> 1;
    const int wn  = wid & 1;

    const float* __restrict__ vab  = va + ((size_t)b * DIM_ + d0) * NA_;
    const float* __restrict__ attb = g_attn + (size_t)b * NA_ * NB_;

    // per-thread fill coordinates (fixed across chunks)
    const int vd = tid >> 3, vm4 = (tid & 7) * 4;          // Vs: +s*16 rows
    const int ak = tid / 28, am4 = (tid - ak * 28) * 4;    // As: +s*4.57 -> recompute

    float acc[2][7][4];
#pragma unroll
    for (int i = 0; i < 2; i++)
#pragma unroll
        for (int j = 0; j < 7; j++)
#pragma unroll
            for (int e = 0; e < 4; e++) acc[i][j][e] = 0.f;

    // ---- async fill of one chunk into buffer p ----
    auto issue = [&](int kc, int p) {
        const uint32_t vbase = sbase + (uint32_t)(p * OB_WORDS) * 4u;
        const uint32_t abase = vbase + 2304u * 4u;
        // Vs: 64 d-rows x 8 uint4 (32 k) = 512 -> 4/thread
#pragma unroll
        for (int s = 0; s < 4; s++) {
            const int d = vd + s * 16;
            const int kcol = kc + vm4;
            const uint32_t sz = (kcol + 3 < NA_) ? 16u : 0u;
            const float* src = vab + (size_t)d * NA_ + (sz ? kcol : 0);
            CP_ASYNC16(vbase + (uint32_t)(d * 36 + vm4) * 4u, src, sz);
        }
        // As: 32 k-rows x 28 uint4 (112 n) = 896 -> 7/thread
#pragma unroll
        for (int s = 0; s < 7; s++) {
            const int u = tid + s * 128;
            const int kk = u / 28, m4 = (u - kk * 28) * 4;
            const int row = kc + kk;
            const uint32_t sz =
                (row < NA_ && n0 + m4 + 3 < NB_) ? 16u : 0u;
            const float* src =
                attb + (sz ? ((size_t)row * NB_ + n0 + m4) : 0);
            CP_ASYNC16(abase + (uint32_t)(kk * 120 + m4) * 4u, src, sz);
        }
        CP_COMMIT();
    };

    issue(0, 0);
    (void)ak; (void)am4;

    for (int c = 0; c < 7; c++) {
        if (c < 6) { issue((c + 1) * 32, (c + 1) & 1); CP_WAIT1(); }
        else       { CP_WAIT0(); }
        __syncthreads();

        const uint32_t* Vs = DYN + (c & 1) * OB_WORDS;
        const uint32_t* As = Vs + 2304;

#pragma unroll
        for (int ks = 0; ks < 4; ks++) {
            const int k0 = ks * 8;
            uint32_t af[2][4];
#pragma unroll
            for (int i = 0; i < 2; i++) {
                const int r = wm * 32 + i * 16 + grp;
                af[i][0] = Vs[r * 36 + k0 + tg];
                af[i][1] = Vs[(r + 8) * 36 + k0 + tg];
                af[i][2] = Vs[r * 36 + k0 + tg + 4];
                af[i][3] = Vs[(r + 8) * 36 + k0 + tg + 4];
            }
            uint32_t bf[7][2];
#pragma unroll
            for (int j = 0; j < 7; j++) {
                const int col = wn * 56 + j * 8 + grp;
                bf[j][0] = As[(k0 + tg) * 120 + col];
                bf[j][1] = As[(k0 + tg + 4) * 120 + col];
            }
#pragma unroll
            for (int i = 0; i < 2; i++)
#pragma unroll
                for (int j = 0; j < 7; j++)
                    MMA_TF32(acc[i][j], af[i], bf[j]);
        }
        __syncthreads();
    }

    const float g0 = gamma[0];
#pragma unroll
    for (int i = 0; i < 2; i++) {
        const int row = d0 + wm * 32 + i * 16 + grp;
#pragma unroll
        for (int j = 0; j < 7; j++) {
            const int col = n0 + wn * 56 + j * 8 + tg * 2;
            if (col < NB_) {
                const size_t o  = ((size_t)b * DIM_ + row) * NB_ + col;
                const size_t o2 = o + (size_t)8 * NB_;
                const float2 w  = *(const float2*)&vbb[o];
                const float2 w2 = *(const float2*)&vbb[o2];
                float2 r, r2;
                r.x  = acc[i][j][0] + w.x  + g0;
                r.y  = acc[i][j][1] + w.y  + g0;
                r2.x = acc[i][j][2] + w2.x + g0;
                r2.y = acc[i][j][3] + w2.y + g0;
                *(float2*)&out[o]  = r;
                *(float2*)&out[o2] = r2;
            }
        }
    }
}

// ---------------------------------------------------------------------------
extern "C" void kernel_launch(void* const* d_in, const int* in_sizes, int n_in,
                              void* d_out, int out_size)
{
    (void)in_sizes; (void)n_in; (void)out_size;
    const float* q     = (const float*)d_in[0];  // [B, Na, Dk]
    const float* va    = (const float*)d_in[1];  // [B, Dim, Na]
    const float* kb    = (const float*)d_in[2];  // [B, Dk, Nb]
    const float* vb    = (const float*)d_in[3];  // [B, Dim, Nb]
    const float* gamma = (const float*)d_in[4];  // [1]
    float* out = (float*)d_out;                  // [B, Dim, Nb]

    convq_kernel<<<dim3(8, B_), 256>>>(q);
    convk_kernel<<<dim3(8, B_), 256>>>(kb);
    energy_mma_kernel<<<dim3(7, B_), 128>>>();

    cudaFuncSetAttribute(out_mma_kernel,
                         cudaFuncAttributeMaxDynamicSharedMemorySize,
                         OUT_SMEM_BYTES);
    out_mma_kernel<<<dim3(16, 2, B_), 128, OUT_SMEM_BYTES>>>(
        va, vb, gamma, out);
}